// round 1
// baseline (speedup 1.0000x reference)
#include <cuda_runtime.h>

// One warp per pose b. Lane l computes keypoints 4l..4l+3 with float4 I/O.
// out layout: (B, 2, N) fp32 -> per pose 256 floats: [u0..u127, v0..v127].

__global__ __launch_bounds__(256) void pose_kernel(
    const float4* __restrict__ quat,      // B x 4
    const float*  __restrict__ kp,        // 3 x 128 (row-major: X row, Y row, Z row)
    const float*  __restrict__ cam,       // 3 x 3
    float4*       __restrict__ out)       // B * 64 float4
{
    const int warp = threadIdx.x >> 5;
    const int lane = threadIdx.x & 31;
    const int b = blockIdx.x * 8 + warp;

    // Quaternion (broadcast load: all lanes same address)
    float4 q = quat[b];
    const float x = q.x, y = q.y, z = q.z, w = q.w;

    // Rotation matrix
    const float xx = x * x, yy = y * y, zz = z * z;
    const float xy = x * y, xz = x * z, yz = y * z;
    const float xw = x * w, yw = y * w, zw = z * w;
    const float r00 = 1.0f - 2.0f * (yy + zz), r01 = 2.0f * (xy - zw), r02 = 2.0f * (xz + yw);
    const float r10 = 2.0f * (xy + zw), r11 = 1.0f - 2.0f * (xx + zz), r12 = 2.0f * (yz - xw);
    const float r20 = 2.0f * (xz - yw), r21 = 2.0f * (yz + xw), r22 = 1.0f - 2.0f * (xx + yy);

    // Camera matrix (broadcast, L1-resident)
    const float k00 = cam[0], k01 = cam[1], k02 = cam[2];
    const float k10 = cam[3], k11 = cam[4], k12 = cam[5];
    const float k20 = cam[6], k21 = cam[7], k22 = cam[8];

    // Fold scale (1/640, 1/480) into rows 0 and 1; t = (0, 0, 0.7)
    const float su = 1.0f / 640.0f, sv = 1.0f / 480.0f;

    // M = diag(su, sv, 1) * K * R ; tc = diag(su, sv, 1) * K * t
    const float m00 = su * (k00 * r00 + k01 * r10 + k02 * r20);
    const float m01 = su * (k00 * r01 + k01 * r11 + k02 * r21);
    const float m02 = su * (k00 * r02 + k01 * r12 + k02 * r22);
    const float m10 = sv * (k10 * r00 + k11 * r10 + k12 * r20);
    const float m11 = sv * (k10 * r01 + k11 * r11 + k12 * r21);
    const float m12 = sv * (k10 * r02 + k11 * r12 + k12 * r22);
    const float m20 = k20 * r00 + k21 * r10 + k22 * r20;
    const float m21 = k20 * r01 + k21 * r11 + k22 * r21;
    const float m22 = k20 * r02 + k21 * r12 + k22 * r22;
    const float t0 = su * (k02 * 0.7f);
    const float t1 = sv * (k12 * 0.7f);
    const float t2 = k22 * 0.7f;

    // Keypoints: 4 consecutive columns per lane, each row is 128 floats = 32 float4
    const float4 px = reinterpret_cast<const float4*>(kp)[lane];
    const float4 py = reinterpret_cast<const float4*>(kp + 128)[lane];
    const float4 pz = reinterpret_cast<const float4*>(kp + 256)[lane];

    float4 uo, vo;
    {
        // element 0
        float i0 = fmaf(m00, px.x, fmaf(m01, py.x, fmaf(m02, pz.x, t0)));
        float i1 = fmaf(m10, px.x, fmaf(m11, py.x, fmaf(m12, pz.x, t1)));
        float i2 = fmaf(m20, px.x, fmaf(m21, py.x, fmaf(m22, pz.x, t2)));
        float rz = __fdividef(1.0f, i2);
        uo.x = i0 * rz; vo.x = i1 * rz;
    }
    {
        float i0 = fmaf(m00, px.y, fmaf(m01, py.y, fmaf(m02, pz.y, t0)));
        float i1 = fmaf(m10, px.y, fmaf(m11, py.y, fmaf(m12, pz.y, t1)));
        float i2 = fmaf(m20, px.y, fmaf(m21, py.y, fmaf(m22, pz.y, t2)));
        float rz = __fdividef(1.0f, i2);
        uo.y = i0 * rz; vo.y = i1 * rz;
    }
    {
        float i0 = fmaf(m00, px.z, fmaf(m01, py.z, fmaf(m02, pz.z, t0)));
        float i1 = fmaf(m10, px.z, fmaf(m11, py.z, fmaf(m12, pz.z, t1)));
        float i2 = fmaf(m20, px.z, fmaf(m21, py.z, fmaf(m22, pz.z, t2)));
        float rz = __fdividef(1.0f, i2);
        uo.z = i0 * rz; vo.z = i1 * rz;
    }
    {
        float i0 = fmaf(m00, px.w, fmaf(m01, py.w, fmaf(m02, pz.w, t0)));
        float i1 = fmaf(m10, px.w, fmaf(m11, py.w, fmaf(m12, pz.w, t1)));
        float i2 = fmaf(m20, px.w, fmaf(m21, py.w, fmaf(m22, pz.w, t2)));
        float rz = __fdividef(1.0f, i2);
        uo.w = i0 * rz; vo.w = i1 * rz;
    }

    // out: pose b owns float4 indices [b*64, b*64+64). u at +lane, v at +32+lane.
    const int base = b * 64;
    out[base + lane]      = uo;
    out[base + 32 + lane] = vo;
}

extern "C" void kernel_launch(void* const* d_in, const int* in_sizes, int n_in,
                              void* d_out, int out_size)
{
    const float4* quat = (const float4*)d_in[0];
    const float*  kp   = (const float*)d_in[1];
    const float*  cam  = (const float*)d_in[2];
    float4* out = (float4*)d_out;

    const int B = in_sizes[0] / 4;          // 65536
    const int blocks = B / 8;               // 8 poses per 256-thread block
    pose_kernel<<<blocks, 256>>>(quat, kp, cam, out);
}